// round 5
// baseline (speedup 1.0000x reference)
#include <cuda_runtime.h>
#include <cuda_bf16.h>

// Problem constants
#define BB   8
#define TT   16
#define HH   16
#define WW   16
#define LL   4096          // T*H*W
#define DIM  128
#define DIN  256
#define DST  16
#define DTR  8
#define KG   2
#define NPOS (BB*LL)       // 32768
#define NBKL (BB*KG*LL)    // 65536
#define PF   8             // scan prefetch depth

// ---------------- scratch (device globals; no allocation allowed) ----------------
__device__ float  g_xh [NPOS * DIN];                 // silu(conv(xh))  (b, p, d)
__device__ float  g_z  [NPOS * DIN];                 // silu(z)
__device__ float2 g_dud[(size_t)NBKL * DIN + PF*DIN];// (delta*u, delta) per (bk, l, d), padded
__device__ float4 g_bc4[(size_t)NBKL * 8  + PF*8];   // (B_j, B_{j+8}, C_j, C_{j+8}) per (bk, l, j)
__device__ float  g_y0 [NPOS * DIN];                 // scan output k=0, natural order
__device__ float  g_y1 [NPOS * DIN];                 // scan output k=1, natural order
__device__ float  g_yz [NPOS * DIN];                 // LN(y)*z

// natural position for spectral-order scan index l: (t,h,w) from l=(h*16+w)*16+t
__device__ __forceinline__ int spe_pos(int l) {
    return ((l & 15) << 8) | (((l >> 8) & 15) << 4) | ((l >> 4) & 15);
}

__device__ __forceinline__ float fast_silu(float x) {
    return x / (1.f + __expf(-x));
}

__device__ __forceinline__ float fast_ex2(float x) {
    float r;
    asm("ex2.approx.f32 %0, %1;" : "=f"(r) : "f"(x));
    return r;
}

// =====================================================================
// Generic 128x128 tile fp32 GEMM:  C[m,n] = sum_k A[m,k] * W[n,k]
// EPI==0: in_proj epilogue (conv affine + silu -> g_xh / g_z)
// EPI==1: plain write to C (out_proj), A is taken from g_yz
// =====================================================================
template<int KDIM, int EPI>
__global__ __launch_bounds__(256) void gemm_nt(
    const float* __restrict__ A_in, const float* __restrict__ W,
    float* __restrict__ C, int N,
    const float* __restrict__ cw, const float* __restrict__ cb)
{
    __shared__ float As[8][128];
    __shared__ float Bs[8][128];

    const float* A = (EPI == 0) ? A_in : g_yz;

    const int tid   = threadIdx.x;
    const int mtile = blockIdx.y * 128;
    const int ntile = blockIdx.x * 128;
    const int lrow  = tid >> 1;          // 0..127
    const int lk4   = (tid & 1) * 4;     // 0 or 4
    const int tx    = tid & 15;
    const int ty    = tid >> 4;

    const float* Ap = A + (size_t)(mtile + lrow) * KDIM + lk4;
    const float* Wp = W + (size_t)(ntile + lrow) * KDIM + lk4;

    float acc[8][8];
    #pragma unroll
    for (int i = 0; i < 8; i++)
        #pragma unroll
        for (int j = 0; j < 8; j++) acc[i][j] = 0.f;

    for (int kc = 0; kc < KDIM; kc += 8) {
        float4 av = *(const float4*)(Ap + kc);
        float4 wv = *(const float4*)(Wp + kc);
        __syncthreads();
        As[lk4+0][lrow] = av.x; As[lk4+1][lrow] = av.y;
        As[lk4+2][lrow] = av.z; As[lk4+3][lrow] = av.w;
        Bs[lk4+0][lrow] = wv.x; Bs[lk4+1][lrow] = wv.y;
        Bs[lk4+2][lrow] = wv.z; Bs[lk4+3][lrow] = wv.w;
        __syncthreads();
        #pragma unroll
        for (int kk = 0; kk < 8; kk++) {
            float4 a0 = *(const float4*)&As[kk][ty*8];
            float4 a1 = *(const float4*)&As[kk][ty*8+4];
            float4 b0 = *(const float4*)&Bs[kk][tx*8];
            float4 b1 = *(const float4*)&Bs[kk][tx*8+4];
            float ar[8] = {a0.x,a0.y,a0.z,a0.w,a1.x,a1.y,a1.z,a1.w};
            float br[8] = {b0.x,b0.y,b0.z,b0.w,b1.x,b1.y,b1.z,b1.w};
            #pragma unroll
            for (int i = 0; i < 8; i++)
                #pragma unroll
                for (int j = 0; j < 8; j++)
                    acc[i][j] = fmaf(ar[i], br[j], acc[i][j]);
        }
    }

    if (EPI == 0) {
        const bool isxh = (ntile < 256);
        const int ocol  = isxh ? (ntile + tx*8) : (ntile - 256 + tx*8);
        float cwv[8], cbv[8];
        if (isxh) {
            #pragma unroll
            for (int j = 0; j < 8; j++) { cwv[j] = cw[ntile + tx*8 + j]; cbv[j] = cb[ntile + tx*8 + j]; }
        }
        #pragma unroll
        for (int i = 0; i < 8; i++) {
            int m = mtile + ty*8 + i;
            float v[8];
            #pragma unroll
            for (int j = 0; j < 8; j++) {
                float t = acc[i][j];
                if (isxh) t = fmaf(t, cwv[j], cbv[j]);
                v[j] = fast_silu(t);
            }
            float* dst = (isxh ? g_xh : g_z) + (size_t)m * DIN + ocol;
            *(float4*)(dst)     = make_float4(v[0], v[1], v[2], v[3]);
            *(float4*)(dst + 4) = make_float4(v[4], v[5], v[6], v[7]);
        }
    } else {
        #pragma unroll
        for (int i = 0; i < 8; i++) {
            int m = mtile + ty*8 + i;
            float* dst = C + (size_t)m * N + ntile + tx*8;
            *(float4*)(dst)     = make_float4(acc[i][0], acc[i][1], acc[i][2], acc[i][3]);
            *(float4*)(dst + 4) = make_float4(acc[i][4], acc[i][5], acc[i][6], acc[i][7]);
        }
    }
}

// =====================================================================
// K2: per (b,k,l) position: 40-dim x_proj, delta = softplus(dts@dt_w + dt_b),
// stage (delta*u, delta) and packed (B, C) for the scan.
// =====================================================================
__global__ __launch_bounds__(256) void k2_proj(
    const float* __restrict__ xpw,   // (2, 40, 256)
    const float* __restrict__ dtw,   // (2, 256, 8)
    const float* __restrict__ dtb)   // (2, 256)
{
    const int pos = blockIdx.x;          // (b*2 + k)*4096 + l
    const int k   = (pos >> 12) & 1;
    const int b   = pos >> 13;
    const int l   = pos & 4095;
    const int p   = (k == 0) ? spe_pos(l) : (4095 - l);
    const int tid = threadIdx.x;

    __shared__ float su[DIN];
    __shared__ float sproj[40];

    const float u = g_xh[(size_t)(b*LL + p) * DIN + tid];
    su[tid] = u;
    __syncthreads();

    // 8 warps x 5 projection outputs each
    const int w    = tid >> 5;
    const int lane = tid & 31;
    const float* wpk = xpw + k * 40 * DIN;
    #pragma unroll
    for (int i = 0; i < 5; i++) {
        int c = w * 5 + i;
        const float* wr = wpk + c * DIN;
        float s = 0.f;
        #pragma unroll
        for (int jj = 0; jj < 8; jj++)
            s = fmaf(su[lane + 32*jj], __ldg(wr + lane + 32*jj), s);
        #pragma unroll
        for (int o = 16; o > 0; o >>= 1)
            s += __shfl_xor_sync(0xffffffffu, s, o);
        if (lane == 0) sproj[c] = s;
    }
    __syncthreads();

    // delta for channel d = tid
    float accv = dtb[k*DIN + tid];
    const float* dwr = dtw + (size_t)(k*DIN + tid) * DTR;
    #pragma unroll
    for (int r = 0; r < DTR; r++)
        accv = fmaf(sproj[r], __ldg(dwr + r), accv);
    // stable softplus
    float delta = fmaxf(accv, 0.f) + __logf(1.f + __expf(-fabsf(accv)));

    g_dud[(size_t)pos * DIN + tid] = make_float2(delta * u, delta);
    if (tid < 8)
        g_bc4[(size_t)pos * 8 + tid] =
            make_float4(sproj[8 + tid], sproj[16 + tid], sproj[24 + tid], sproj[32 + tid]);
}

// =====================================================================
// K3: selective scan. 8 lanes per (b,k,d); lane j owns states n=j and n=j+8.
// 256 blocks x 128 threads. Register prefetch pipeline depth PF=8.
// =====================================================================
__global__ __launch_bounds__(128) void k3_scan(const float* __restrict__ A_logs)
{
    const int bk = blockIdx.x >> 4;          // 0..15
    const int b  = bk >> 1, k = bk & 1;
    const int d0 = (blockIdx.x & 15) << 4;   // 16 channels per block
    const int tid = threadIdx.x;
    const int g  = tid >> 3;                 // group within block (channel)
    const int j  = tid & 7;                  // lane within group
    const int d  = d0 + g;

    const float L2E = 1.4426950408889634f;
    // A pre-multiplied by log2(e) so dA = ex2(delta * A*log2e)
    const float A1 = -expf(A_logs[(size_t)(k*DIN + d) * DST + j])     * L2E;
    const float A2 = -expf(A_logs[(size_t)(k*DIN + d) * DST + j + 8]) * L2E;

    const float2* pd = g_dud + (size_t)bk * LL * DIN + d;
    const float4* pb = g_bc4 + (size_t)bk * LL * 8   + j;
    float* yout = (k == 0 ? g_y0 : g_y1) + (size_t)b * LL * DIN + d;

    float2 dbuf[PF];
    float4 bbuf[PF];
    #pragma unroll
    for (int i = 0; i < PF; i++) {
        dbuf[i] = __ldcs(pd + (size_t)i * DIN);
        bbuf[i] = __ldg (pb + (size_t)i * 8);
    }

    float h1 = 0.f, h2 = 0.f;

    for (int l0 = 0; l0 < LL; l0 += PF) {
        #pragma unroll
        for (int q = 0; q < PF; q++) {
            const int l = l0 + q;
            float2 dc = dbuf[q];
            float4 bc = bbuf[q];
            // prefetch step l+PF (arrays padded so last block stays in-bounds)
            dbuf[q] = __ldcs(pd + (size_t)(l + PF) * DIN);
            bbuf[q] = __ldg (pb + (size_t)(l + PF) * 8);

            float dA1 = fast_ex2(dc.y * A1);
            float dA2 = fast_ex2(dc.y * A2);
            h1 = fmaf(dA1, h1, dc.x * bc.x);
            h2 = fmaf(dA2, h2, dc.x * bc.y);
            float y = fmaf(h1, bc.z, h2 * bc.w);
            y += __shfl_xor_sync(0xffffffffu, y, 1, 8);
            y += __shfl_xor_sync(0xffffffffu, y, 2, 8);
            y += __shfl_xor_sync(0xffffffffu, y, 4, 8);
            if (j == 0) {
                int p = (k == 0) ? spe_pos(l) : (4095 - l);
                yout[(size_t)p * DIN] = y;
            }
        }
    }
}

// =====================================================================
// K4a: y = y0 + y1 + (Ds0+Ds1)*xh ; LayerNorm(256) ; * silu(z)  -> g_yz
// =====================================================================
__global__ __launch_bounds__(256) void k4a_ln(
    const float* __restrict__ Ds,
    const float* __restrict__ lnw, const float* __restrict__ lnb)
{
    const int m = blockIdx.x;
    const int d = threadIdx.x;
    const size_t idx = (size_t)m * DIN + d;

    float y = g_y0[idx] + g_y1[idx] + (Ds[d] + Ds[DIN + d]) * g_xh[idx];

    __shared__ float red[8];
    float s = y;
    #pragma unroll
    for (int o = 16; o > 0; o >>= 1) s += __shfl_xor_sync(0xffffffffu, s, o);
    if ((d & 31) == 0) red[d >> 5] = s;
    __syncthreads();
    float tot = 0.f;
    #pragma unroll
    for (int w = 0; w < 8; w++) tot += red[w];
    const float mu = tot * (1.f / 256.f);
    __syncthreads();

    const float e = y - mu;
    float s2 = e * e;
    #pragma unroll
    for (int o = 16; o > 0; o >>= 1) s2 += __shfl_xor_sync(0xffffffffu, s2, o);
    if ((d & 31) == 0) red[d >> 5] = s2;
    __syncthreads();
    float tot2 = 0.f;
    #pragma unroll
    for (int w = 0; w < 8; w++) tot2 += red[w];
    const float rstd = rsqrtf(tot2 * (1.f / 256.f) + 1e-5f);

    g_yz[idx] = fmaf(e * rstd, lnw[d], lnb[d]) * g_z[idx];
}

// =====================================================================
extern "C" void kernel_launch(void* const* d_in, const int* in_sizes, int n_in,
                              void* d_out, int out_size)
{
    const float* x          = (const float*)d_in[0];
    const float* in_proj_w  = (const float*)d_in[1];
    const float* conv_w     = (const float*)d_in[2];
    const float* conv_b     = (const float*)d_in[3];
    const float* x_proj_w   = (const float*)d_in[4];
    const float* dt_w       = (const float*)d_in[5];
    const float* dt_b       = (const float*)d_in[6];
    const float* A_logs     = (const float*)d_in[7];
    const float* Ds         = (const float*)d_in[8];
    const float* ln_w       = (const float*)d_in[9];
    const float* ln_b       = (const float*)d_in[10];
    const float* out_proj_w = (const float*)d_in[11];
    float* out = (float*)d_out;

    // K1: in_proj GEMM (32768 x 512 x 128) + conv affine + silu
    gemm_nt<DIM, 0><<<dim3(4, 256), 256>>>(x, in_proj_w, nullptr, 0, conv_w, conv_b);

    // K2: x_proj + dt projection + softplus staging
    k2_proj<<<NBKL, 256>>>(x_proj_w, dt_w, dt_b);

    // K3: dual-direction selective scan
    k3_scan<<<256, 128>>>(A_logs);

    // K4a: combine + LayerNorm + gate
    k4a_ln<<<NPOS, 256>>>(Ds, ln_w, ln_b);

    // K4b: out_proj GEMM (32768 x 128 x 256)
    gemm_nt<DIN, 1><<<dim3(1, 256), 256>>>(nullptr, out_proj_w, out, DIM, nullptr, nullptr);
}

// round 9
// speedup vs baseline: 1.3727x; 1.3727x over previous
#include <cuda_runtime.h>
#include <cuda_bf16.h>

// Problem constants
#define BB   8
#define TT   16
#define HH   16
#define WW   16
#define LL   4096          // T*H*W
#define DIM  128
#define DIN  256
#define DST  16
#define DTR  8
#define KG   2
#define NPOS (BB*LL)       // 32768
#define NBKL (BB*KG*LL)    // 65536
#define PF   8             // scan prefetch depth

// ---------------- scratch (device globals; no allocation allowed) ----------------
__device__ float  g_xh [NPOS * DIN];                 // silu(conv(xh))  (b, p, d)
__device__ float  g_z  [NPOS * DIN];                 // silu(z)
__device__ float2 g_dud[(size_t)NBKL * DIN + PF*DIN];// (delta*u, delta) per (bk, l, d), padded
__device__ float4 g_bc4[(size_t)NBKL * 8  + PF*8];   // (B_j, B_{j+8}, C_j, C_{j+8}) per (bk, l, j)
__device__ float  g_y0 [NPOS * DIN];                 // scan output k=0, natural order
__device__ float  g_y1 [NPOS * DIN];                 // scan output k=1, natural order
__device__ float  g_yz [NPOS * DIN];                 // LN(y)*z

// natural position for spectral-order scan index l: (t,h,w) from l=(h*16+w)*16+t
__device__ __forceinline__ int spe_pos(int l) {
    return ((l & 15) << 8) | (((l >> 8) & 15) << 4) | ((l >> 4) & 15);
}

__device__ __forceinline__ float fast_silu(float x) {
    return x / (1.f + __expf(-x));
}

__device__ __forceinline__ float fast_ex2(float x) {
    float r;
    asm("ex2.approx.f32 %0, %1;" : "=f"(r) : "f"(x));
    return r;
}

// ---------------- tf32 mma helpers ----------------
__device__ __forceinline__ unsigned cvt_tf32(float x) {
    unsigned r;
    asm("cvt.rna.tf32.f32 %0, %1;" : "=r"(r) : "f"(x));
    return r;
}
__device__ __forceinline__ void split_tf32(float v, unsigned& hi, unsigned& lo) {
    hi = cvt_tf32(v);
    float hif = __uint_as_float(hi);
    lo = cvt_tf32(v - hif);
}
__device__ __forceinline__ void mma_tf32(float (&c)[4],
    unsigned a0, unsigned a1, unsigned a2, unsigned a3,
    unsigned b0, unsigned b1)
{
    asm volatile(
        "mma.sync.aligned.m16n8k8.row.col.f32.tf32.tf32.f32 "
        "{%0,%1,%2,%3}, {%4,%5,%6,%7}, {%8,%9}, {%0,%1,%2,%3};"
        : "+f"(c[0]), "+f"(c[1]), "+f"(c[2]), "+f"(c[3])
        : "r"(a0), "r"(a1), "r"(a2), "r"(a3), "r"(b0), "r"(b1));
}

// =====================================================================
// 3xTF32 tensor-core GEMM:  C[m,n] = sum_k A[m,k] * W[n,k]
// Block 256 thr (8 warps, 2(M)x4(N)), block tile 128x128, warp tile 64x32.
// EPI==0: in_proj epilogue (conv affine + silu -> g_xh / g_z)
// EPI==1: out_proj (A from g_yz, plain write to C, N=128)
// =====================================================================
template<int KDIM, int EPI>
__global__ __launch_bounds__(256) void gemm_tf32(
    const float* __restrict__ A_in, const float* __restrict__ W,
    float* __restrict__ C,
    const float* __restrict__ cw, const float* __restrict__ cb)
{
    __shared__ float As[8][136];
    __shared__ float Bs[8][136];

    const float* A = (EPI == 0) ? A_in : g_yz;

    const int tid  = threadIdx.x;
    const int wid  = tid >> 5;
    const int lane = tid & 31;
    const int gid  = lane >> 2;       // 0..7
    const int tid4 = lane & 3;        // 0..3
    const int wm   = (wid & 1) * 64;  // warp m offset in block tile
    const int wn   = (wid >> 1) * 32; // warp n offset
    const int mtile = blockIdx.y * 128;
    const int ntile = blockIdx.x * 128;
    const int lrow  = tid >> 1;       // 0..127
    const int lk4   = (tid & 1) * 4;  // 0 or 4

    const float* Ap = A + (size_t)(mtile + lrow) * KDIM + lk4;
    const float* Wp = W + (size_t)(ntile + lrow) * KDIM + lk4;

    float acc[4][4][4];
    #pragma unroll
    for (int mt = 0; mt < 4; mt++)
        #pragma unroll
        for (int nt = 0; nt < 4; nt++)
            #pragma unroll
            for (int e = 0; e < 4; e++) acc[mt][nt][e] = 0.f;

    for (int kc = 0; kc < KDIM; kc += 8) {
        float4 av = *(const float4*)(Ap + kc);
        float4 wv = *(const float4*)(Wp + kc);
        __syncthreads();
        As[lk4+0][lrow] = av.x; As[lk4+1][lrow] = av.y;
        As[lk4+2][lrow] = av.z; As[lk4+3][lrow] = av.w;
        Bs[lk4+0][lrow] = wv.x; Bs[lk4+1][lrow] = wv.y;
        Bs[lk4+2][lrow] = wv.z; Bs[lk4+3][lrow] = wv.w;
        __syncthreads();

        // A fragments (hi/lo) for 4 m-tiles
        unsigned ah[4][4], al[4][4];
        #pragma unroll
        for (int mt = 0; mt < 4; mt++) {
            const int rb = wm + mt*16 + gid;
            split_tf32(As[tid4  ][rb  ], ah[mt][0], al[mt][0]);
            split_tf32(As[tid4  ][rb+8], ah[mt][1], al[mt][1]);
            split_tf32(As[tid4+4][rb  ], ah[mt][2], al[mt][2]);
            split_tf32(As[tid4+4][rb+8], ah[mt][3], al[mt][3]);
        }
        // B fragments (hi/lo) for 4 n-tiles
        unsigned bh[4][2], bl[4][2];
        #pragma unroll
        for (int nt = 0; nt < 4; nt++) {
            const int nb = wn + nt*8 + gid;
            split_tf32(Bs[tid4  ][nb], bh[nt][0], bl[nt][0]);
            split_tf32(Bs[tid4+4][nb], bh[nt][1], bl[nt][1]);
        }
        #pragma unroll
        for (int mt = 0; mt < 4; mt++)
            #pragma unroll
            for (int nt = 0; nt < 4; nt++) {
                mma_tf32(acc[mt][nt], ah[mt][0], ah[mt][1], ah[mt][2], ah[mt][3],
                         bh[nt][0], bh[nt][1]);
                mma_tf32(acc[mt][nt], al[mt][0], al[mt][1], al[mt][2], al[mt][3],
                         bh[nt][0], bh[nt][1]);
                mma_tf32(acc[mt][nt], ah[mt][0], ah[mt][1], ah[mt][2], ah[mt][3],
                         bl[nt][0], bl[nt][1]);
            }
    }

    if (EPI == 0) {
        const bool isxh = (ntile < 256);
        #pragma unroll
        for (int nt = 0; nt < 4; nt++) {
            const int gcol = ntile + wn + nt*8 + 2*tid4;
            const int ocol = isxh ? gcol : (gcol - 256);
            float cw0 = 0.f, cw1 = 0.f, cb0 = 0.f, cb1 = 0.f;
            if (isxh) {
                cw0 = __ldg(cw + gcol);     cw1 = __ldg(cw + gcol + 1);
                cb0 = __ldg(cb + gcol);     cb1 = __ldg(cb + gcol + 1);
            }
            float* base = isxh ? g_xh : g_z;
            #pragma unroll
            for (int mt = 0; mt < 4; mt++) {
                const int r0 = mtile + wm + mt*16 + gid;
                float t0 = acc[mt][nt][0], t1 = acc[mt][nt][1];
                float t2 = acc[mt][nt][2], t3 = acc[mt][nt][3];
                if (isxh) {
                    t0 = fmaf(t0, cw0, cb0); t1 = fmaf(t1, cw1, cb1);
                    t2 = fmaf(t2, cw0, cb0); t3 = fmaf(t3, cw1, cb1);
                }
                *(float2*)(base + (size_t)r0 * DIN + ocol) =
                    make_float2(fast_silu(t0), fast_silu(t1));
                *(float2*)(base + (size_t)(r0 + 8) * DIN + ocol) =
                    make_float2(fast_silu(t2), fast_silu(t3));
            }
        }
    } else {
        #pragma unroll
        for (int nt = 0; nt < 4; nt++) {
            const int gcol = ntile + wn + nt*8 + 2*tid4;
            #pragma unroll
            for (int mt = 0; mt < 4; mt++) {
                const int r0 = mtile + wm + mt*16 + gid;
                *(float2*)(C + (size_t)r0 * DIM + gcol) =
                    make_float2(acc[mt][nt][0], acc[mt][nt][1]);
                *(float2*)(C + (size_t)(r0 + 8) * DIM + gcol) =
                    make_float2(acc[mt][nt][2], acc[mt][nt][3]);
            }
        }
    }
}

// =====================================================================
// K2: warp-per-position (x4 positions per warp), weights in smem.
// 40-dim x_proj dots via full shfl-xor reduce, delta = softplus(dts@dt_w+dt_b),
// stage (delta*u, delta) and packed (B, C) for the scan.
// grid 2048 blocks x 256 thr; block = 32 consecutive l of one bk.
// =====================================================================
__global__ __launch_bounds__(256) void k2_proj(
    const float* __restrict__ xpw,   // (2, 40, 256)
    const float* __restrict__ dtw,   // (2, 256, 8)
    const float* __restrict__ dtb)   // (2, 256)
{
    const int blk = blockIdx.x;
    const int bk  = blk >> 7;            // 0..15
    const int l0  = (blk & 127) << 5;    // 32 l per block
    const int b   = bk >> 1, k = bk & 1;
    const int tid = threadIdx.x, wid = tid >> 5, lane = tid & 31;

    __shared__ float wsm[40 * DIN];      // 40 KB
    __shared__ float dwsm[DIN * 9];      // padded dt_w rows (9 floats) ~9 KB

    const float* wpk = xpw + k * 40 * DIN;
    for (int i = tid; i < 40 * DIN; i += 256) wsm[i] = wpk[i];
    const float* dwk = dtw + (size_t)k * DIN * DTR;
    for (int i = tid; i < DIN; i += 32) {
        // each of 8 "i-slots" handled; copy row i (8 floats) by one thread group
    }
    // simple padded copy: 256 threads, each copies 8 rows' single element pattern
    for (int i = tid; i < DIN * DTR; i += 256) {
        int d = i / DTR, r = i % DTR;
        dwsm[d * 9 + r] = dwk[i];
    }
    __syncthreads();

    // 4 positions for this warp
    const int lbase = l0 + wid * 4;
    float u[4][8];
    #pragma unroll
    for (int q = 0; q < 4; q++) {
        const int l = lbase + q;
        const int p = (k == 0) ? spe_pos(l) : (4095 - l);
        const float* up = g_xh + (size_t)(b * LL + p) * DIN + lane;
        #pragma unroll
        for (int i = 0; i < 8; i++) u[q][i] = up[32 * i];   // channel d = lane+32i
    }

    float dts[4][8];
    float bcv[4][4];
    #pragma unroll
    for (int c = 0; c < 40; c++) {
        float wr[8];
        #pragma unroll
        for (int i = 0; i < 8; i++) wr[i] = wsm[c * DIN + lane + 32 * i];
        #pragma unroll
        for (int q = 0; q < 4; q++) {
            float s = 0.f;
            #pragma unroll
            for (int i = 0; i < 8; i++) s = fmaf(u[q][i], wr[i], s);
            #pragma unroll
            for (int o = 16; o > 0; o >>= 1) s += __shfl_xor_sync(0xffffffffu, s, o);
            if (c < 8) {
                dts[q][c] = s;
            } else if (lane == ((c - 8) & 7)) {
                bcv[q][(c - 8) >> 3] = s;
            }
        }
    }

    #pragma unroll
    for (int q = 0; q < 4; q++) {
        const size_t pos = (size_t)bk * LL + (lbase + q);
        #pragma unroll
        for (int i = 0; i < 8; i++) {
            const int d = lane + 32 * i;
            float a = __ldg(dtb + k * DIN + d);
            #pragma unroll
            for (int r = 0; r < DTR; r++)
                a = fmaf(dts[q][r], dwsm[d * 9 + r], a);
            // stable softplus
            float delta = fmaxf(a, 0.f) + __logf(1.f + __expf(-fabsf(a)));
            g_dud[pos * DIN + d] = make_float2(delta * u[q][i], delta);
        }
        if (lane < 8)
            g_bc4[pos * 8 + lane] = make_float4(bcv[q][0], bcv[q][1], bcv[q][2], bcv[q][3]);
    }
}

// =====================================================================
// K3: selective scan. 8 lanes per (b,k,d); lane j owns states n=j and n=j+8.
// 256 blocks x 128 threads. Register prefetch pipeline depth PF=8.
// =====================================================================
__global__ __launch_bounds__(128) void k3_scan(const float* __restrict__ A_logs)
{
    const int bk = blockIdx.x >> 4;          // 0..15
    const int b  = bk >> 1, k = bk & 1;
    const int d0 = (blockIdx.x & 15) << 4;   // 16 channels per block
    const int tid = threadIdx.x;
    const int g  = tid >> 3;                 // group within block (channel)
    const int j  = tid & 7;                  // lane within group
    const int d  = d0 + g;

    const float L2E = 1.4426950408889634f;
    const float A1 = -expf(A_logs[(size_t)(k*DIN + d) * DST + j])     * L2E;
    const float A2 = -expf(A_logs[(size_t)(k*DIN + d) * DST + j + 8]) * L2E;

    const float2* pd = g_dud + (size_t)bk * LL * DIN + d;
    const float4* pb = g_bc4 + (size_t)bk * LL * 8   + j;
    float* yout = (k == 0 ? g_y0 : g_y1) + (size_t)b * LL * DIN + d;

    float2 dbuf[PF];
    float4 bbuf[PF];
    #pragma unroll
    for (int i = 0; i < PF; i++) {
        dbuf[i] = __ldcs(pd + (size_t)i * DIN);
        bbuf[i] = __ldg (pb + (size_t)i * 8);
    }

    float h1 = 0.f, h2 = 0.f;

    for (int l0 = 0; l0 < LL; l0 += PF) {
        #pragma unroll
        for (int q = 0; q < PF; q++) {
            const int l = l0 + q;
            float2 dc = dbuf[q];
            float4 bc = bbuf[q];
            dbuf[q] = __ldcs(pd + (size_t)(l + PF) * DIN);
            bbuf[q] = __ldg (pb + (size_t)(l + PF) * 8);

            float dA1 = fast_ex2(dc.y * A1);
            float dA2 = fast_ex2(dc.y * A2);
            h1 = fmaf(dA1, h1, dc.x * bc.x);
            h2 = fmaf(dA2, h2, dc.x * bc.y);
            float y = fmaf(h1, bc.z, h2 * bc.w);
            y += __shfl_xor_sync(0xffffffffu, y, 1, 8);
            y += __shfl_xor_sync(0xffffffffu, y, 2, 8);
            y += __shfl_xor_sync(0xffffffffu, y, 4, 8);
            if (j == 0) {
                int p = (k == 0) ? spe_pos(l) : (4095 - l);
                yout[(size_t)p * DIN] = y;
            }
        }
    }
}

// =====================================================================
// K4a: y = y0 + y1 + (Ds0+Ds1)*xh ; LayerNorm(256) ; * silu(z)  -> g_yz
// =====================================================================
__global__ __launch_bounds__(256) void k4a_ln(
    const float* __restrict__ Ds,
    const float* __restrict__ lnw, const float* __restrict__ lnb)
{
    const int m = blockIdx.x;
    const int d = threadIdx.x;
    const size_t idx = (size_t)m * DIN + d;

    float y = g_y0[idx] + g_y1[idx] + (Ds[d] + Ds[DIN + d]) * g_xh[idx];

    __shared__ float red[8];
    float s = y;
    #pragma unroll
    for (int o = 16; o > 0; o >>= 1) s += __shfl_xor_sync(0xffffffffu, s, o);
    if ((d & 31) == 0) red[d >> 5] = s;
    __syncthreads();
    float tot = 0.f;
    #pragma unroll
    for (int w = 0; w < 8; w++) tot += red[w];
    const float mu = tot * (1.f / 256.f);
    __syncthreads();

    const float e = y - mu;
    float s2 = e * e;
    #pragma unroll
    for (int o = 16; o > 0; o >>= 1) s2 += __shfl_xor_sync(0xffffffffu, s2, o);
    if ((d & 31) == 0) red[d >> 5] = s2;
    __syncthreads();
    float tot2 = 0.f;
    #pragma unroll
    for (int w = 0; w < 8; w++) tot2 += red[w];
    const float rstd = rsqrtf(tot2 * (1.f / 256.f) + 1e-5f);

    g_yz[idx] = fmaf(e * rstd, lnw[d], lnb[d]) * g_z[idx];
}

// =====================================================================
extern "C" void kernel_launch(void* const* d_in, const int* in_sizes, int n_in,
                              void* d_out, int out_size)
{
    const float* x          = (const float*)d_in[0];
    const float* in_proj_w  = (const float*)d_in[1];
    const float* conv_w     = (const float*)d_in[2];
    const float* conv_b     = (const float*)d_in[3];
    const float* x_proj_w   = (const float*)d_in[4];
    const float* dt_w       = (const float*)d_in[5];
    const float* dt_b       = (const float*)d_in[6];
    const float* A_logs     = (const float*)d_in[7];
    const float* Ds         = (const float*)d_in[8];
    const float* ln_w       = (const float*)d_in[9];
    const float* ln_b       = (const float*)d_in[10];
    const float* out_proj_w = (const float*)d_in[11];
    float* out = (float*)d_out;

    // K1: in_proj GEMM (32768 x 512 x 128), 3xTF32 tensor cores + conv affine + silu
    gemm_tf32<DIM, 0><<<dim3(4, 256), 256>>>(x, in_proj_w, nullptr, conv_w, conv_b);

    // K2: x_proj + dt projection + softplus staging (warp-per-position x4)
    k2_proj<<<2048, 256>>>(x_proj_w, dt_w, dt_b);

    // K3: dual-direction selective scan
    k3_scan<<<256, 128>>>(A_logs);

    // K4a: combine + LayerNorm + gate
    k4a_ln<<<NPOS, 256>>>(Ds, ln_w, ln_b);

    // K4b: out_proj GEMM (32768 x 128 x 256), 3xTF32 tensor cores
    gemm_tf32<DIN, 1><<<dim3(1, 256), 256>>>(nullptr, out_proj_w, out, nullptr, nullptr);
}